// round 1
// baseline (speedup 1.0000x reference)
#include <cuda_runtime.h>

#define NPTS 8192
#define KN   32
#define DIM  256
#define DIMH 128
#define DOUT 512
#define LDT  36   // padded row stride (floats) for transposed smem tiles; 36*4=144B keeps float4 alignment

// scratch (allocation-free rule: __device__ globals)
__device__ float g_qattn[NPTS * DIM];
__device__ float g_respre[NPTS * DIM];

// ---------------------------------------------------------------------------
// packed f32x2 FMA (Blackwell FFMA2): d = a*b + d  on two lanes
// ---------------------------------------------------------------------------
union F2U { float2 f; unsigned long long u; };

__device__ __forceinline__ void ffma2(float2& d, const float2 a, const float2 b) {
    F2U du, au, bu;
    du.f = d; au.f = a; bu.f = b;
    asm("fma.rn.f32x2 %0, %1, %2, %0;" : "+l"(du.u) : "l"(au.u), "l"(bu.u));
    d = du.f;
}

// ---------------------------------------------------------------------------
// Column GEMM: thread computes 32 rows of one output column c.
// At: transposed A in smem, At[kk*LDT + r], r = 0..31 (32 valid floats/row).
// W:  global weights, row-major [KK][NC].
// acc[i] packs rows (2i, 2i+1).
// ---------------------------------------------------------------------------
template <int KK, int NC>
__device__ __forceinline__ void colgemm(const float* __restrict__ At,
                                        const float* __restrict__ W,
                                        int c, float2 (&acc)[16]) {
#pragma unroll 4
    for (int kk = 0; kk < KK; ++kk) {
        float w = __ldg(W + kk * NC + c);
        float2 w2 = make_float2(w, w);
        const float4* a4 = reinterpret_cast<const float4*>(At + kk * LDT);
#pragma unroll
        for (int i = 0; i < 8; ++i) {
            float4 a = a4[i];
            ffma2(acc[2 * i],     make_float2(a.x, a.y), w2);
            ffma2(acc[2 * i + 1], make_float2(a.z, a.w), w2);
        }
    }
}

// ---------------------------------------------------------------------------
// Kernel 0: copy xyz_q passthrough into out[0:24576]
// ---------------------------------------------------------------------------
extern "C" __global__ void copy_xyz_kernel(const float* __restrict__ src,
                                           float* __restrict__ dst, int n) {
    int i = blockIdx.x * blockDim.x + threadIdx.x;
    if (i < n) dst[i] = src[i];
}

// ---------------------------------------------------------------------------
// Kernel 1: q_attn = feats_q @ Wq   (32-row tiles, 256 CTAs)
// ---------------------------------------------------------------------------
extern "C" __global__ void __launch_bounds__(256)
qproj_kernel(const float* __restrict__ feats_q, const float* __restrict__ Wq) {
    __shared__ float At[DIM * LDT];
    const int n0 = blockIdx.x * 32;
    const int f = threadIdx.x;
#pragma unroll
    for (int r = 0; r < 32; ++r)
        At[f * LDT + r] = feats_q[(size_t)(n0 + r) * DIM + f];
    __syncthreads();

    float2 acc[16];
#pragma unroll
    for (int i = 0; i < 16; ++i) acc[i] = make_float2(0.f, 0.f);
    colgemm<DIM, DIM>(At, Wq, f, acc);

#pragma unroll
    for (int i = 0; i < 16; ++i) {
        g_qattn[(size_t)(n0 + 2 * i) * DIM + f]     = acc[i].x;
        g_qattn[(size_t)(n0 + 2 * i + 1) * DIM + f] = acc[i].y;
    }
}

// ---------------------------------------------------------------------------
// Kernel 2: fused per-point block. One CTA per point, 256 threads.
// Thread f owns feature column f throughout; softmax over K=32 is
// thread-local; smem only carries transposed A-operands for the GEMMs.
// ---------------------------------------------------------------------------
extern "C" __global__ void __launch_bounds__(256, 2)
fused_kernel(const float* __restrict__ xyz_q, const float* __restrict__ xyz_kv,
             const float* __restrict__ feats_kv,
             const float* __restrict__ Wk, const float* __restrict__ Wv,
             const float* __restrict__ d1w, const float* __restrict__ d1b,
             const float* __restrict__ d2w, const float* __restrict__ d2b,
             const float* __restrict__ g1w, const float* __restrict__ g1b,
             const float* __restrict__ g2w, const float* __restrict__ g2b) {
    extern __shared__ float sm[];
    float* Ft  = sm;                  // [DIM][LDT]  feats_kv^T, later reused as relu(h@g1)^T
    float* Ht  = Ft + DIM * LDT;      // [DIM][LDT]  h^T
    float* H1t = Ht + DIM * LDT;      // [DIMH][LDT] relu(rel@d1)^T
    float* qs  = H1t + DIMH * LDT;    // [DIM]

    const int n = blockIdx.x;
    const int f = threadIdx.x;

    // stage feats_kv (32x256) transposed
    const float* fkv = feats_kv + (size_t)n * KN * DIM;
#pragma unroll
    for (int k = 0; k < KN; ++k)
        Ft[f * LDT + k] = fkv[k * DIM + f];
    qs[f] = g_qattn[(size_t)n * DIM + f];

    // pos MLP layer 1: hidden1[k][j] = relu(rel . d1w[:,j] + d1b[j]), stored transposed
    {
        const int j  = f & (DIMH - 1);
        const int k0 = (f >> 7) * 16;
        const float w0 = d1w[j], w1 = d1w[DIMH + j], w2v = d1w[2 * DIMH + j];
        const float b = d1b[j];
        const float qx = xyz_q[n * 3 + 0], qy = xyz_q[n * 3 + 1], qz = xyz_q[n * 3 + 2];
#pragma unroll
        for (int k = k0; k < k0 + 16; ++k) {
            const float* p = xyz_kv + ((size_t)n * KN + k) * 3;
            float rx = qx - p[0], ry = qy - p[1], rz = qz - p[2];
            float h = fmaf(rx, w0, fmaf(ry, w1, fmaf(rz, w2v, b)));
            H1t[j * LDT + k] = fmaxf(h, 0.f);
        }
    }
    __syncthreads();

    // pe column (32 regs as 16 float2)
    float2 pe[16];
    {
        float b = d2b[f];
#pragma unroll
        for (int i = 0; i < 16; ++i) pe[i] = make_float2(b, b);
    }
    colgemm<DIMH, DIM>(H1t, d2w, f, pe);

    // k column, then h = q - k + pe -> Ht (transposed)
    float2 acc[16];
#pragma unroll
    for (int i = 0; i < 16; ++i) acc[i] = make_float2(0.f, 0.f);
    colgemm<DIM, DIM>(Ft, Wk, f, acc);
    {
        const float qv = qs[f];
#pragma unroll
        for (int i = 0; i < 16; ++i) {
            Ht[f * LDT + 2 * i]     = qv - acc[i].x + pe[i].x;
            Ht[f * LDT + 2 * i + 1] = qv - acc[i].y + pe[i].y;
        }
    }

    // v column, vpe = v + pe (pe regs retired into vpe)
#pragma unroll
    for (int i = 0; i < 16; ++i) acc[i] = make_float2(0.f, 0.f);
    colgemm<DIM, DIM>(Ft, Wv, f, acc);
    float2 vpe[16];
#pragma unroll
    for (int i = 0; i < 16; ++i)
        vpe[i] = make_float2(acc[i].x + pe[i].x, acc[i].y + pe[i].y);

    __syncthreads();  // Ht written by all; all done reading Ft

    // gamma layer 1: relu(h @ g1 + b), written transposed into Ft
    {
        float b = g1b[f];
#pragma unroll
        for (int i = 0; i < 16; ++i) acc[i] = make_float2(b, b);
    }
    colgemm<DIM, DIM>(Ht, g1w, f, acc);
#pragma unroll
    for (int i = 0; i < 16; ++i) {
        Ft[f * LDT + 2 * i]     = fmaxf(acc[i].x, 0.f);
        Ft[f * LDT + 2 * i + 1] = fmaxf(acc[i].y, 0.f);
    }
    __syncthreads();

    // gamma layer 2: attn logits
    {
        float b = g2b[f];
#pragma unroll
        for (int i = 0; i < 16; ++i) acc[i] = make_float2(b, b);
    }
    colgemm<DIM, DIM>(Ft, g2w, f, acc);

    // softmax over the 32 neighbors (thread-local) + weighted sum with vpe
    float m = -3.402823466e38f;
#pragma unroll
    for (int i = 0; i < 16; ++i) {
        m = fmaxf(m, acc[i].x);
        m = fmaxf(m, acc[i].y);
    }
    float ssum = 0.f, rsum = 0.f;
#pragma unroll
    for (int i = 0; i < 16; ++i) {
        float ex = __expf(acc[i].x - m);
        ssum += ex; rsum += ex * vpe[i].x;
        float ey = __expf(acc[i].y - m);
        ssum += ey; rsum += ey * vpe[i].y;
    }
    g_respre[(size_t)n * DIM + f] = rsum / ssum;
}

// ---------------------------------------------------------------------------
// Kernel 3: out = res_pre @ out_w + out_b  (32-row tiles, 512 threads/CTA)
// ---------------------------------------------------------------------------
extern "C" __global__ void __launch_bounds__(512)
outproj_kernel(const float* __restrict__ ow, const float* __restrict__ ob,
               float* __restrict__ out, long long ofs) {
    __shared__ float At[DIM * LDT];
    const int n0 = blockIdx.x * 32;
    const int t = threadIdx.x;
    if (t < DIM) {
#pragma unroll
        for (int r = 0; r < 32; ++r)
            At[t * LDT + r] = g_respre[(size_t)(n0 + r) * DIM + t];
    }
    __syncthreads();

    float2 acc[16];
    {
        float b = ob[t];
#pragma unroll
        for (int i = 0; i < 16; ++i) acc[i] = make_float2(b, b);
    }
    colgemm<DIM, DOUT>(At, ow, t, acc);

    float* dst = out + ofs;
#pragma unroll
    for (int i = 0; i < 16; ++i) {
        dst[(size_t)(n0 + 2 * i) * DOUT + t]     = acc[i].x;
        dst[(size_t)(n0 + 2 * i + 1) * DOUT + t] = acc[i].y;
    }
}

// ---------------------------------------------------------------------------
extern "C" void kernel_launch(void* const* d_in, const int* in_sizes, int n_in,
                              void* d_out, int out_size) {
    const float* xyz_q    = (const float*)d_in[0];
    const float* feats_q  = (const float*)d_in[1];
    const float* xyz_kv   = (const float*)d_in[2];
    const float* feats_kv = (const float*)d_in[3];
    const float* Wq       = (const float*)d_in[4];
    const float* Wk       = (const float*)d_in[5];
    const float* Wv       = (const float*)d_in[6];
    const float* d1w      = (const float*)d_in[7];
    const float* d1b      = (const float*)d_in[8];
    const float* d2w      = (const float*)d_in[9];
    const float* d2b      = (const float*)d_in[10];
    const float* g1w      = (const float*)d_in[11];
    const float* g1b      = (const float*)d_in[12];
    const float* g2w      = (const float*)d_in[13];
    const float* g2b      = (const float*)d_in[14];
    const float* ow       = (const float*)d_in[15];
    const float* obias    = (const float*)d_in[16];
    float* out = (float*)d_out;

    // output = (xyz_q, res): xyz passthrough first (if out_size includes it)
    long long ofs = (long long)out_size - (long long)NPTS * DOUT;
    if (ofs < 0) ofs = 0;
    if (ofs > 0)
        copy_xyz_kernel<<<(int)((ofs + 255) / 256), 256>>>(xyz_q, out, (int)ofs);

    qproj_kernel<<<NPTS / 32, 256>>>(feats_q, Wq);

    const int smem_main = (2 * DIM * LDT + DIMH * LDT + DIM) * (int)sizeof(float);  // 93184 B
    cudaFuncSetAttribute(fused_kernel, cudaFuncAttributeMaxDynamicSharedMemorySize, smem_main);
    fused_kernel<<<NPTS, 256, smem_main>>>(xyz_q, xyz_kv, feats_kv,
                                           Wk, Wv, d1w, d1b, d2w, d2b,
                                           g1w, g1b, g2w, g2b);

    outproj_kernel<<<NPTS / 32, 512>>>(ow, obias, out, ofs);
}

// round 3
// speedup vs baseline: 4.3724x; 4.3724x over previous
#include <cuda_runtime.h>
#include <cuda_fp16.h>
#include <cstdint>

#define NPTS 8192
#define KN   32
#define DIM  256
#define DIMH 128
#define DOUT 512
#define LDT  36

// ---------------- device scratch (allocation-free rule) ----------------
__device__ float  g_qattn[NPTS * DIM];
__device__ float  g_respre[NPTS * DIM];
__device__ __half g_WkTn[DIM * DIM];    // -Wk, transposed [n][k] fp16
__device__ __half g_WvT [DIM * DIM];    // [n][k]
__device__ __half g_g1T [DIM * DIM];
__device__ __half g_g2T [DIM * DIM];
__device__ __half g_d2T [DIM * DIMH];   // [n=256][k=128]

// ---------------- weight conversion: dst[n*K+k] = scale * src[k*N+n] ----
extern "C" __global__ void convert_w(const float* __restrict__ src,
                                     __half* __restrict__ dst,
                                     int K, int N, float scale) {
    int idx = blockIdx.x * blockDim.x + threadIdx.x;
    if (idx < K * N) {
        int n = idx / K, k = idx - n * K;
        dst[idx] = __float2half(scale * src[k * N + n]);
    }
}

// ---------------- xyz passthrough ----------------
extern "C" __global__ void copy_xyz_kernel(const float* __restrict__ src,
                                           float* __restrict__ dst, int n) {
    int i = blockIdx.x * blockDim.x + threadIdx.x;
    if (i < n) dst[i] = src[i];
}

// ---------------- fp32 column-GEMM helpers (q / out projections) -------
union F2U { float2 f; unsigned long long u; };
__device__ __forceinline__ void ffma2(float2& d, const float2 a, const float2 b) {
    F2U du, au, bu; du.f = d; au.f = a; bu.f = b;
    asm("fma.rn.f32x2 %0, %1, %2, %0;" : "+l"(du.u) : "l"(au.u), "l"(bu.u));
    d = du.f;
}

template <int KK, int NC>
__device__ __forceinline__ void colgemm(const float* __restrict__ At,
                                        const float* __restrict__ W,
                                        int c, float2 (&acc)[16]) {
#pragma unroll 4
    for (int kk = 0; kk < KK; ++kk) {
        float w = __ldg(W + kk * NC + c);
        float2 w2 = make_float2(w, w);
        const float4* a4 = reinterpret_cast<const float4*>(At + kk * LDT);
#pragma unroll
        for (int i = 0; i < 8; ++i) {
            float4 a = a4[i];
            ffma2(acc[2 * i],     make_float2(a.x, a.y), w2);
            ffma2(acc[2 * i + 1], make_float2(a.z, a.w), w2);
        }
    }
}

extern "C" __global__ void __launch_bounds__(256)
qproj_kernel(const float* __restrict__ feats_q, const float* __restrict__ Wq) {
    __shared__ float At[DIM * LDT];
    const int n0 = blockIdx.x * 32;
    const int f = threadIdx.x;
#pragma unroll
    for (int r = 0; r < 32; ++r) {
        At[f * LDT + r] = feats_q[(size_t)(n0 + r) * DIM + f];
    }
    __syncthreads();
    float2 acc[16];
#pragma unroll
    for (int i = 0; i < 16; ++i) { acc[i] = make_float2(0.f, 0.f); }
    colgemm<DIM, DIM>(At, Wq, f, acc);
#pragma unroll
    for (int i = 0; i < 16; ++i) {
        g_qattn[(size_t)(n0 + 2 * i) * DIM + f]     = acc[i].x;
        g_qattn[(size_t)(n0 + 2 * i + 1) * DIM + f] = acc[i].y;
    }
}

extern "C" __global__ void __launch_bounds__(512)
outproj_kernel(const float* __restrict__ ow, const float* __restrict__ ob,
               float* __restrict__ out, long long ofs) {
    __shared__ float At[DIM * LDT];
    const int n0 = blockIdx.x * 32;
    const int t = threadIdx.x;
    if (t < DIM) {
#pragma unroll
        for (int r = 0; r < 32; ++r) {
            At[t * LDT + r] = g_respre[(size_t)(n0 + r) * DIM + t];
        }
    }
    __syncthreads();
    float2 acc[16];
    float b = ob[t];
#pragma unroll
    for (int i = 0; i < 16; ++i) { acc[i] = make_float2(b, b); }
    colgemm<DIM, DOUT>(At, ow, t, acc);
    float* dst = out + ofs;
#pragma unroll
    for (int i = 0; i < 16; ++i) {
        dst[(size_t)(n0 + 2 * i) * DOUT + t]     = acc[i].x;
        dst[(size_t)(n0 + 2 * i + 1) * DOUT + t] = acc[i].y;
    }
}

// =======================================================================
// Fused tensor-core kernel: CTA = 4 points (128 rows x 256 feats),
// 512 threads = 16 warps, warp w owns output columns [16w, 16w+16).
// =======================================================================

__device__ __forceinline__ unsigned int swz(int row, int cb, int rb) {
    return (unsigned int)(row * rb + (cb ^ ((row & 7) << 4)));
}

// one accumulation pass: acc += A(smem, swizzled, row-bytes rb) @ WT^T
__device__ __forceinline__ void gemm_tile(float (&acc)[8][2][4],
                                          unsigned int abase, int rb,
                                          const __half* __restrict__ WT,
                                          const int Kw, const int ksteps,
                                          int n0, int lane) {
    const int g   = lane >> 2;
    const int tig = lane & 3;
    const int lr  = (lane & 7) + ((lane >> 3) & 1) * 8;  // ldmatrix row
    const int lcb = ((lane >> 4) & 1) * 16;              // ldmatrix col-byte half
#pragma unroll 2
    for (int ks = 0; ks < ksteps; ++ks) {
        unsigned int b0[2], b1[2];
#pragma unroll
        for (int nt = 0; nt < 2; ++nt) {
            const __half* wp = WT + (size_t)(n0 + nt * 8 + g) * Kw + ks * 16 + 2 * tig;
            b0[nt] = __ldg((const unsigned int*)wp);
            b1[nt] = __ldg((const unsigned int*)(wp + 8));
        }
#pragma unroll
        for (int mt = 0; mt < 8; ++mt) {
            unsigned int a0, a1, a2, a3;
            unsigned int ad = abase + swz(mt * 16 + lr, ks * 32 + lcb, rb);
            asm volatile("ldmatrix.sync.aligned.m8n8.x4.shared.b16 {%0,%1,%2,%3}, [%4];\n"
                         : "=r"(a0), "=r"(a1), "=r"(a2), "=r"(a3) : "r"(ad));
#pragma unroll
            for (int nt = 0; nt < 2; ++nt) {
                asm volatile(
                    "mma.sync.aligned.m16n8k16.row.col.f32.f16.f16.f32 "
                    "{%0,%1,%2,%3},{%4,%5,%6,%7},{%8,%9},{%0,%1,%2,%3};\n"
                    : "+f"(acc[mt][nt][0]), "+f"(acc[mt][nt][1]),
                      "+f"(acc[mt][nt][2]), "+f"(acc[mt][nt][3])
                    : "r"(a0), "r"(a1), "r"(a2), "r"(a3),
                      "r"(b0[nt]), "r"(b1[nt]));
            }
        }
    }
}

// store accum tile (optionally relu'ed) as fp16 into swizzled 512B-row buffer
__device__ __forceinline__ void store_tile(float (&acc)[8][2][4], char* buf,
                                           int n0, int lane, bool relu) {
    const int g = lane >> 2, tig = lane & 3;
#pragma unroll
    for (int mt = 0; mt < 8; ++mt) {
#pragma unroll
        for (int nt = 0; nt < 2; ++nt) {
            int col = n0 + nt * 8 + 2 * tig;
            float x0 = acc[mt][nt][0], x1 = acc[mt][nt][1];
            float x2 = acc[mt][nt][2], x3 = acc[mt][nt][3];
            if (relu) {
                x0 = fmaxf(x0, 0.f); x1 = fmaxf(x1, 0.f);
                x2 = fmaxf(x2, 0.f); x3 = fmaxf(x3, 0.f);
            }
            __half2 lo = __floats2half2_rn(x0, x1);
            __half2 hi = __floats2half2_rn(x2, x3);
            *(__half2*)(buf + swz(mt * 16 + g,     col * 2, 512)) = lo;
            *(__half2*)(buf + swz(mt * 16 + g + 8, col * 2, 512)) = hi;
        }
    }
}

extern "C" __global__ void __launch_bounds__(512, 1)
fused_tc_kernel(const float* __restrict__ xyz_q, const float* __restrict__ xyz_kv,
                const float* __restrict__ feats_kv,
                const float* __restrict__ d1w, const float* __restrict__ d1b,
                const float* __restrict__ d2b,
                const float* __restrict__ g1b, const float* __restrict__ g2b) {
    extern __shared__ __half sm[];
    char* base = (char*)sm;
    char* Fbuf = base;                        // 128 x 512B fp16 swizzled
    char* Hbuf = base + 65536;                // h tile
    char* Vbuf = base + 131072;               // vpe tile
    char* H1b  = base + 196608;               // 128 x 256B fp16 swizzled
    __half* qbuf = (__half*)(base + 229376);  // 4 x 256 fp16

    unsigned int smb = (unsigned int)__cvta_generic_to_shared(sm);
    const unsigned int Fb = smb, Hb = smb + 65536u, H1 = smb + 196608u;

    const int tid  = threadIdx.x;
    const int lane = tid & 31;
    const int wrp  = tid >> 5;
    const int n0   = wrp * 16;
    const int p0   = blockIdx.x * 4;
    const int g    = lane >> 2, tig = lane & 3;

    // ---- stage feats_kv tile (128 x 256 fp32 -> fp16 swizzled) ----
    {
        const float4* src = (const float4*)(feats_kv + (size_t)p0 * KN * DIM);
        for (int i = tid; i < 128 * 64; i += 512) {
            int row = i >> 6, c4 = i & 63;
            float4 v = __ldg(src + (size_t)row * 64 + c4);
            __half2 h01 = __floats2half2_rn(v.x, v.y);
            __half2 h23 = __floats2half2_rn(v.z, v.w);
            uint2 u = make_uint2(*(unsigned int*)&h01, *(unsigned int*)&h23);
            *(uint2*)(Fbuf + swz(row, c4 * 8, 512)) = u;
        }
    }
    // ---- stage q rows (4 x 256) as fp16 ----
    for (int i = tid; i < 4 * DIM; i += 512) {
        int p = i >> 8, n = i & 255;
        qbuf[i] = __float2half(g_qattn[(size_t)(p0 + p) * DIM + n]);
    }
    // ---- H1 = relu(rel @ d1 + b)  (128 x 128 fp16 swizzled) ----
    {
        int row = tid >> 2;
        int c0  = (tid & 3) * 32;
        int p   = row >> 5, k = row & 31;
        float qx = __ldg(xyz_q + (p0 + p) * 3 + 0);
        float qy = __ldg(xyz_q + (p0 + p) * 3 + 1);
        float qz = __ldg(xyz_q + (p0 + p) * 3 + 2);
        const float* pk = xyz_kv + ((size_t)(p0 + p) * KN + k) * 3;
        float rx = qx - __ldg(pk + 0), ry = qy - __ldg(pk + 1), rz = qz - __ldg(pk + 2);
#pragma unroll 4
        for (int c = c0; c < c0 + 32; c += 2) {
            float h0 = fmaf(rx, __ldg(d1w + c),     fmaf(ry, __ldg(d1w + 128 + c),     fmaf(rz, __ldg(d1w + 256 + c),     __ldg(d1b + c))));
            float h1 = fmaf(rx, __ldg(d1w + c + 1), fmaf(ry, __ldg(d1w + 128 + c + 1), fmaf(rz, __ldg(d1w + 256 + c + 1), __ldg(d1b + c + 1))));
            __half2 hh = __floats2half2_rn(fmaxf(h0, 0.f), fmaxf(h1, 0.f));
            *(__half2*)(H1b + swz(row, c * 2, 256)) = hh;
        }
    }
    __syncthreads();

    // per-thread column slots: s = nt*2+ci -> col
    int cols[4]; float d2bv[4], g1bv[4], g2bv[4];
#pragma unroll
    for (int s = 0; s < 4; ++s) {
        cols[s] = n0 + (s >> 1) * 8 + 2 * tig + (s & 1);
        d2bv[s] = __ldg(d2b + cols[s]);
        g1bv[s] = __ldg(g1b + cols[s]);
        g2bv[s] = __ldg(g2b + cols[s]);
    }
    float qq[4][4];
#pragma unroll
    for (int p = 0; p < 4; ++p) {
#pragma unroll
        for (int s = 0; s < 4; ++s) {
            qq[p][s] = __half2float(qbuf[p * 256 + cols[s]]);
        }
    }

    float acc[8][2][4];

    // ---- pass A: h = q + d2b + F@(-Wk) + H1@d2 -> Hbuf ----
#pragma unroll
    for (int mt = 0; mt < 8; ++mt) {
#pragma unroll
        for (int nt = 0; nt < 2; ++nt) {
#pragma unroll
            for (int i = 0; i < 4; ++i) {
                int s = nt * 2 + (i & 1);
                acc[mt][nt][i] = qq[mt >> 1][s] + d2bv[s];
            }
        }
    }
    gemm_tile(acc, Fb, 512, g_WkTn, 256, 16, n0, lane);
    gemm_tile(acc, H1, 256, g_d2T, 128, 8, n0, lane);
    store_tile(acc, Hbuf, n0, lane, false);

    // ---- pass B: vpe = d2b + F@Wv + H1@d2 -> Vbuf ----
#pragma unroll
    for (int mt = 0; mt < 8; ++mt) {
#pragma unroll
        for (int nt = 0; nt < 2; ++nt) {
#pragma unroll
            for (int i = 0; i < 4; ++i) {
                acc[mt][nt][i] = d2bv[nt * 2 + (i & 1)];
            }
        }
    }
    gemm_tile(acc, Fb, 512, g_WvT, 256, 16, n0, lane);
    gemm_tile(acc, H1, 256, g_d2T, 128, 8, n0, lane);
    store_tile(acc, Vbuf, n0, lane, false);
    __syncthreads();

    // ---- pass C: A1 = relu(h @ g1 + b) -> Fbuf ----
#pragma unroll
    for (int mt = 0; mt < 8; ++mt) {
#pragma unroll
        for (int nt = 0; nt < 2; ++nt) {
#pragma unroll
            for (int i = 0; i < 4; ++i) {
                acc[mt][nt][i] = g1bv[nt * 2 + (i & 1)];
            }
        }
    }
    gemm_tile(acc, Hb, 512, g_g1T, 256, 16, n0, lane);
    store_tile(acc, Fbuf, n0, lane, true);
    __syncthreads();

    // ---- pass D: logits = A1 @ g2 + b ; softmax over 32 neighbors ----
#pragma unroll
    for (int mt = 0; mt < 8; ++mt) {
#pragma unroll
        for (int nt = 0; nt < 2; ++nt) {
#pragma unroll
            for (int i = 0; i < 4; ++i) {
                acc[mt][nt][i] = g2bv[nt * 2 + (i & 1)];
            }
        }
    }
    gemm_tile(acc, Fb, 512, g_g2T, 256, 16, n0, lane);

#pragma unroll
    for (int gr = 0; gr < 4; ++gr) {
        const int m0 = 2 * gr, m1 = 2 * gr + 1;
        const int r0 = 32 * gr + g, r1 = r0 + 8, r2 = r0 + 16, r3 = r0 + 24;
#pragma unroll
        for (int s = 0; s < 4; ++s) {
            const int nt = s >> 1, ci = s & 1;
            float v0 = acc[m0][nt][ci],     v1 = acc[m0][nt][ci + 2];
            float v2 = acc[m1][nt][ci],     v3 = acc[m1][nt][ci + 2];
            float mx = fmaxf(fmaxf(v0, v1), fmaxf(v2, v3));
            mx = fmaxf(mx, __shfl_xor_sync(0xffffffffu, mx, 4));
            mx = fmaxf(mx, __shfl_xor_sync(0xffffffffu, mx, 8));
            mx = fmaxf(mx, __shfl_xor_sync(0xffffffffu, mx, 16));
            float e0 = __expf(v0 - mx), e1 = __expf(v1 - mx);
            float e2 = __expf(v2 - mx), e3 = __expf(v3 - mx);
            const int cb = cols[s] * 2;
            float w0 = e0 * __half2float(*(__half*)(Vbuf + swz(r0, cb, 512)));
            float w1 = e1 * __half2float(*(__half*)(Vbuf + swz(r1, cb, 512)));
            float w2 = e2 * __half2float(*(__half*)(Vbuf + swz(r2, cb, 512)));
            float w3 = e3 * __half2float(*(__half*)(Vbuf + swz(r3, cb, 512)));
            float ss = (e0 + e1) + (e2 + e3);
            float ws = (w0 + w1) + (w2 + w3);
            ss += __shfl_xor_sync(0xffffffffu, ss, 4);
            ws += __shfl_xor_sync(0xffffffffu, ws, 4);
            ss += __shfl_xor_sync(0xffffffffu, ss, 8);
            ws += __shfl_xor_sync(0xffffffffu, ws, 8);
            ss += __shfl_xor_sync(0xffffffffu, ss, 16);
            ws += __shfl_xor_sync(0xffffffffu, ws, 16);
            if (g == 0) {
                g_respre[(size_t)(p0 + gr) * DIM + cols[s]] = ws / ss;
            }
        }
    }
}

// =======================================================================
extern "C" void kernel_launch(void* const* d_in, const int* in_sizes, int n_in,
                              void* d_out, int out_size) {
    const float* xyz_q    = (const float*)d_in[0];
    const float* feats_q  = (const float*)d_in[1];
    const float* xyz_kv   = (const float*)d_in[2];
    const float* feats_kv = (const float*)d_in[3];
    const float* Wq       = (const float*)d_in[4];
    const float* Wk       = (const float*)d_in[5];
    const float* Wv       = (const float*)d_in[6];
    const float* d1w      = (const float*)d_in[7];
    const float* d1b      = (const float*)d_in[8];
    const float* d2w      = (const float*)d_in[9];
    const float* d2b      = (const float*)d_in[10];
    const float* g1w      = (const float*)d_in[11];
    const float* g1b      = (const float*)d_in[12];
    const float* g2w      = (const float*)d_in[13];
    const float* g2b      = (const float*)d_in[14];
    const float* ow       = (const float*)d_in[15];
    const float* obias    = (const float*)d_in[16];
    float* out = (float*)d_out;

    long long ofs = (long long)out_size - (long long)NPTS * DOUT;
    if (ofs < 0) ofs = 0;
    if (ofs > 0)
        copy_xyz_kernel<<<(int)((ofs + 255) / 256), 256>>>(xyz_q, out, (int)ofs);

    // fp16 transposed weights (Wk negated)
    {
        __half *wk, *wv, *w1, *w2, *wd2;
        cudaGetSymbolAddress((void**)&wk,  g_WkTn);
        cudaGetSymbolAddress((void**)&wv,  g_WvT);
        cudaGetSymbolAddress((void**)&w1,  g_g1T);
        cudaGetSymbolAddress((void**)&w2,  g_g2T);
        cudaGetSymbolAddress((void**)&wd2, g_d2T);
        convert_w<<<(DIM * DIM + 255) / 256, 256>>>(Wk,  wk,  DIM,  DIM, -1.f);
        convert_w<<<(DIM * DIM + 255) / 256, 256>>>(Wv,  wv,  DIM,  DIM,  1.f);
        convert_w<<<(DIM * DIM + 255) / 256, 256>>>(g1w, w1,  DIM,  DIM,  1.f);
        convert_w<<<(DIM * DIM + 255) / 256, 256>>>(g2w, w2,  DIM,  DIM,  1.f);
        convert_w<<<(DIMH * DIM + 255) / 256, 256>>>(d2w, wd2, DIMH, DIM, 1.f);
    }

    qproj_kernel<<<NPTS / 32, 256>>>(feats_q, Wq);

    const int smem_fused = 231424;  // 3*64KB tiles + 32KB H1 + 2KB q
    cudaFuncSetAttribute(fused_tc_kernel, cudaFuncAttributeMaxDynamicSharedMemorySize, smem_fused);
    fused_tc_kernel<<<NPTS / 4, 512, smem_fused>>>(xyz_q, xyz_kv, feats_kv,
                                                   d1w, d1b, d2b, g1b, g2b);

    outproj_kernel<<<NPTS / 32, 512>>>(ow, obias, out, ofs);
}